// round 11
// baseline (speedup 1.0000x reference)
#include <cuda_runtime.h>

#define N_USERS 100000
#define M_ITEMS 50000
#define NTOT    150000
#define EMBED   64
#define BATCH   8192
#define NNZ     2400000
#define HALF    (NNZ / 2)
#define TILE    1024                       // elements per scan tile
#define SBLK    ((NTOT + TILE - 1) / TILE) // 147 scan blocks
#define NQ      (3 * BATCH)                // query rows (user, item_i, item_j)

// Static device scratch (no allocation allowed).
__device__ float g_A[(size_t)NTOT * EMBED];   // layer-2 output
__device__ float g_B[(size_t)NTOT * EMBED];   // layer-1 output
__device__ float g_Sq[(size_t)NQ * EMBED];    // per-query running light_out sum
__device__ int   g_cnt[NTOT + 1];
__device__ int   g_rs[NTOT + 1];              // CSR row starts
__device__ int   g_cur[NTOT];                 // scatter cursors
__device__ int   g_part[SBLK + 1];            // per-tile partial sums
__device__ int2  g_edge[NNZ];                 // packed (dst, val-bits), grouped by src

// Map query slot q (0..NQ) -> node id.
__device__ __forceinline__ int qnode(unsigned int q, const int* __restrict__ user,
                                     const int* __restrict__ item_i,
                                     const int* __restrict__ item_j) {
    unsigned int which = q / BATCH;
    unsigned int b = q % BATCH;
    if (which == 0) return user[b];
    if (which == 1) return item_i[b] + N_USERS;
    return item_j[b] + N_USERS;
}

// Zero counters + reg_loss slot (layer-1 gather reads emb0 inputs directly now).
__global__ void k_zero(float* __restrict__ out) {
    unsigned int i = blockIdx.x * blockDim.x + threadIdx.x;
    if (i <= NTOT) g_cnt[i] = 0;
    if (i == 0) out[2 * BATCH] = 0.0f;
}

// Histogram using the mirrored structure: one thread per undirected edge
// increments both endpoint counters (edge appears as (u->it) and (it->u)).
__global__ void k_hist(const int* __restrict__ src, const int* __restrict__ dst) {
    unsigned int i = blockIdx.x * blockDim.x + threadIdx.x;
    if (i >= HALF) return;
    int s = src[i];
    int d = dst[i];
    atomicAdd(&g_cnt[s], 1);
    atomicAdd(&g_cnt[d], 1);
}

// ---- Parallel exclusive scan of g_cnt[0..NTOT) -> g_rs, g_cur ----
__global__ void k_scanA() {
    int b = blockIdx.x;
    int t = threadIdx.x;                 // 256 threads, 4 elems each
    int base = b * TILE + t * 4;
    int s = 0;
    #pragma unroll
    for (int j = 0; j < 4; j++) {
        int idx = base + j;
        if (idx < NTOT) s += g_cnt[idx];
    }
    #pragma unroll
    for (int o = 16; o; o >>= 1) s += __shfl_xor_sync(0xffffffffu, s, o);
    __shared__ int sh[8];
    if ((t & 31) == 0) sh[t >> 5] = s;
    __syncthreads();
    if (t == 0) {
        int tot = 0;
        #pragma unroll
        for (int k = 0; k < 8; k++) tot += sh[k];
        g_part[b] = tot;
    }
}

__global__ void k_scanB() {
    __shared__ int sp[256];
    int t = threadIdx.x;
    sp[t] = (t < SBLK) ? g_part[t] : 0;
    __syncthreads();
    #pragma unroll
    for (int o = 1; o < 256; o <<= 1) {
        int v = (t >= o) ? sp[t - o] : 0;
        __syncthreads();
        sp[t] += v;
        __syncthreads();
    }
    if (t < SBLK) g_part[t] = (t == 0) ? 0 : sp[t - 1];   // exclusive
    if (t == 0) g_rs[NTOT] = NNZ;
}

__global__ void k_scanC() {
    __shared__ int sh[256];
    int b = blockIdx.x;
    int t = threadIdx.x;
    int base = b * TILE + t * 4;
    int c[4];
    int s = 0;
    #pragma unroll
    for (int j = 0; j < 4; j++) {
        int idx = base + j;
        c[j] = (idx < NTOT) ? g_cnt[idx] : 0;
        s += c[j];
    }
    sh[t] = s;
    __syncthreads();
    #pragma unroll
    for (int o = 1; o < 256; o <<= 1) {
        int v = (t >= o) ? sh[t - o] : 0;
        __syncthreads();
        sh[t] += v;
        __syncthreads();
    }
    int run = g_part[b] + ((t == 0) ? 0 : sh[t - 1]);
    #pragma unroll
    for (int j = 0; j < 4; j++) {
        int idx = base + j;
        if (idx < NTOT) { g_rs[idx] = run; g_cur[idx] = run; }
        run += c[j];
    }
}

// Reorder using the mirrored structure: one thread per undirected edge inserts
// both directed records, reusing the (s, d, v) loads.
__global__ void k_reorder(const int* __restrict__ src, const int* __restrict__ dst,
                          const float* __restrict__ vals) {
    unsigned int i = blockIdx.x * blockDim.x + threadIdx.x;
    if (i >= HALF) return;
    int s = src[i];
    int d = dst[i];
    int vb = __float_as_int(vals[i]);
    int p1 = atomicAdd(&g_cur[s], 1);
    g_edge[p1] = make_int2(d, vb);
    int p2 = atomicAdd(&g_cur[d], 1);
    g_edge[p2] = make_int2(s, vb);
}

// One warp per node, MLP-16 pipelined full-table gather.
// mode 0: input = emb0 (eu/ei inputs), output = g_B
// mode 1: input = g_B,                 output = g_A
__global__ void k_gather(const float* __restrict__ eu, const float* __restrict__ ei,
                         int mode) {
    unsigned int gw = (blockIdx.x * blockDim.x + threadIdx.x) >> 5;
    if (gw >= NTOT) return;
    unsigned int lane = threadIdx.x & 31u;
    int beg = g_rs[gw];
    int end = g_rs[gw + 1];
    float ax = 0.0f, ay = 0.0f;
    for (int base = beg; base < end; base += 32) {
        int n = end - base; if (n > 32) n = 32;
        int2 ed = make_int2(0, 0);                       // pad: row 0, weight 0
        if (base + (int)lane < end) ed = __ldg(&g_edge[base + lane]);
        for (int k = 0; k < n; k += 16) {
            float2 x[16];
            float  v[16];
            #pragma unroll
            for (int j = 0; j < 16; j++) {
                int idx = k + j;
                int d  = __shfl_sync(0xffffffffu, ed.x, idx & 31);
                int vb = __shfl_sync(0xffffffffu, ed.y, idx & 31);
                v[j] = (idx < n) ? __int_as_float(vb) : 0.0f;
                const float2* row;
                if (mode) {
                    row = reinterpret_cast<const float2*>(g_B + (size_t)d * EMBED);
                } else {
                    row = (d < N_USERS)
                        ? reinterpret_cast<const float2*>(eu + (size_t)d * EMBED)
                        : reinterpret_cast<const float2*>(ei + (size_t)(d - N_USERS) * EMBED);
                }
                x[j] = row[lane];                         // 16 loads in flight
            }
            #pragma unroll
            for (int j = 0; j < 16; j++) {
                ax = fmaf(v[j], x[j].x, ax);
                ay = fmaf(v[j], x[j].y, ay);
            }
        }
    }
    size_t idx = (size_t)gw * (EMBED / 2) + lane;
    float* outp = mode ? g_A : g_B;
    reinterpret_cast<float2*>(outp)[idx] = make_float2(ax, ay);
}

// Fused: S_q = emb0 row at each query slot AND reg_loss accumulation.
__global__ void k_regq(const int* __restrict__ user, const int* __restrict__ item_i,
                       const int* __restrict__ item_j,
                       const float* __restrict__ eu, const float* __restrict__ ei,
                       float* __restrict__ out) {
    unsigned int gw = (blockIdx.x * blockDim.x + threadIdx.x) >> 5;
    unsigned int lane = threadIdx.x & 31u;
    float s = 0.0f;
    if (gw < NQ) {
        int node = qnode(gw, user, item_i, item_j);
        const float2* row = (node < N_USERS)
            ? reinterpret_cast<const float2*>(eu + (size_t)node * EMBED)
            : reinterpret_cast<const float2*>(ei + (size_t)(node - N_USERS) * EMBED);
        float2 v = row[lane];
        reinterpret_cast<float2*>(g_Sq)[(size_t)gw * (EMBED / 2) + lane] = v;
        s = v.x * v.x + v.y * v.y;
    }
    #pragma unroll
    for (int o = 16; o; o >>= 1) s += __shfl_xor_sync(0xffffffffu, s, o);
    __shared__ float sh[8];
    unsigned int w = threadIdx.x >> 5;
    if (lane == 0) sh[w] = s;
    __syncthreads();
    if (threadIdx.x == 0) {
        float t = 0.0f;
        #pragma unroll
        for (int k = 0; k < 8; k++) t += sh[k];
        atomicAdd(out + 2 * BATCH, t * (0.5f / (float)BATCH));
    }
}

// S_q += table rows at queried slots. sel 1: g_B, sel 0: g_A.
__global__ void k_qacc(const int* __restrict__ user, const int* __restrict__ item_i,
                       const int* __restrict__ item_j, int sel) {
    unsigned int gw = (blockIdx.x * blockDim.x + threadIdx.x) >> 5;
    if (gw >= NQ) return;
    unsigned int lane = threadIdx.x & 31u;
    int node = qnode(gw, user, item_i, item_j);
    const float* tab = sel ? g_B : g_A;
    float2 v = reinterpret_cast<const float2*>(tab)[(size_t)node * (EMBED / 2) + lane];
    float2* sq = reinterpret_cast<float2*>(g_Sq) + (size_t)gw * (EMBED / 2) + lane;
    float2 s = *sq;
    *sq = make_float2(s.x + v.x, s.y + v.y);
}

// Layer 3 at queried rows only: S_q[q] += sum val_e * g_A[dst_e].
__global__ void k_qgather(const int* __restrict__ user, const int* __restrict__ item_i,
                          const int* __restrict__ item_j) {
    unsigned int gw = (blockIdx.x * blockDim.x + threadIdx.x) >> 5;
    if (gw >= NQ) return;
    unsigned int lane = threadIdx.x & 31u;
    const float2* __restrict__ in = reinterpret_cast<const float2*>(g_A);
    int node = qnode(gw, user, item_i, item_j);
    int beg = g_rs[node];
    int end = g_rs[node + 1];
    float ax = 0.0f, ay = 0.0f;
    for (int base = beg; base < end; base += 32) {
        int n = end - base; if (n > 32) n = 32;
        int2 ed = make_int2(0, 0);
        if (base + (int)lane < end) ed = __ldg(&g_edge[base + lane]);
        for (int k = 0; k < n; k += 16) {
            float2 x[16];
            float  v[16];
            #pragma unroll
            for (int j = 0; j < 16; j++) {
                int idx = k + j;
                int d  = __shfl_sync(0xffffffffu, ed.x, idx & 31);
                int vb = __shfl_sync(0xffffffffu, ed.y, idx & 31);
                v[j] = (idx < n) ? __int_as_float(vb) : 0.0f;
                x[j] = in[(size_t)d * (EMBED / 2) + lane];
            }
            #pragma unroll
            for (int j = 0; j < 16; j++) {
                ax = fmaf(v[j], x[j].x, ax);
                ay = fmaf(v[j], x[j].y, ay);
            }
        }
    }
    float2* sq = reinterpret_cast<float2*>(g_Sq) + (size_t)gw * (EMBED / 2) + lane;
    float2 s = *sq;
    *sq = make_float2(s.x + ax, s.y + ay);
}

// Predictions from S_q: pred_i[b] = dot(Sq[b], Sq[BATCH+b]) / 16, same for j.
__global__ void k_pred(float* __restrict__ out) {
    unsigned int gw = (blockIdx.x * blockDim.x + threadIdx.x) >> 5;
    unsigned int lane = threadIdx.x & 31u;
    if (gw >= BATCH) return;
    const float2* sq = reinterpret_cast<const float2*>(g_Sq);
    float2 ue = sq[(size_t)gw * (EMBED / 2) + lane];
    float2 ie = sq[(size_t)(BATCH + gw) * (EMBED / 2) + lane];
    float2 je = sq[(size_t)(2 * BATCH + gw) * (EMBED / 2) + lane];
    float di = ue.x * ie.x + ue.y * ie.y;
    float dj = ue.x * je.x + ue.y * je.y;
    #pragma unroll
    for (int o = 16; o; o >>= 1) {
        di += __shfl_xor_sync(0xffffffffu, di, o);
        dj += __shfl_xor_sync(0xffffffffu, dj, o);
    }
    if (lane == 0) {
        out[gw]         = di * 0.0625f;   // (1/4)*(1/4)
        out[BATCH + gw] = dj * 0.0625f;
    }
}

extern "C" void kernel_launch(void* const* d_in, const int* in_sizes, int n_in,
                              void* d_out, int out_size) {
    const int*   user   = (const int*)d_in[0];
    const int*   item_i = (const int*)d_in[1];
    const int*   item_j = (const int*)d_in[2];
    const int*   esrc   = (const int*)d_in[5];
    const int*   edst   = (const int*)d_in[6];
    const float* evals  = (const float*)d_in[7];
    const float* eu     = (const float*)d_in[8];
    const float* ei     = (const float*)d_in[9];
    float* out = (float*)d_out;

    const int hb = (HALF + 255) / 256;               // per-undirected-edge kernels
    const int wb = (NTOT * 32 + 255) / 256;          // warp-per-node gather
    const int qb = (NQ * 32 + 255) / 256;            // warp-per-query kernels

    k_zero<<<(NTOT + 256) / 256, 256>>>(out);

    // Build CSR (by src) fresh each launch, exploiting mirrored edge layout.
    k_hist<<<hb, 256>>>(esrc, edst);
    k_scanA<<<SBLK, 256>>>();
    k_scanB<<<1, 256>>>();
    k_scanC<<<SBLK, 256>>>();
    k_reorder<<<hb, 256>>>(esrc, edst, evals);

    // S_q = emb0 at queried rows (fused with reg_loss).
    k_regq<<<qb, 256>>>(user, item_i, item_j, eu, ei, out);

    // Layer 1: emb0 -> B ; S_q += B at queried rows.
    k_gather<<<wb, 256>>>(eu, ei, 0);
    k_qacc<<<qb, 256>>>(user, item_i, item_j, 1);

    // Layer 2: B -> A ; S_q += A at queried rows.
    k_gather<<<wb, 256>>>(eu, ei, 1);
    k_qacc<<<qb, 256>>>(user, item_i, item_j, 0);

    // Layer 3 only at queried rows: S_q += gather(A).
    k_qgather<<<qb, 256>>>(user, item_i, item_j);

    k_pred<<<(BATCH * 32) / 256, 256>>>(out);
}

// round 12
// speedup vs baseline: 1.4447x; 1.4447x over previous
#include <cuda_runtime.h>

#define N_USERS 100000
#define M_ITEMS 50000
#define NTOT    150000
#define EMBED   64
#define BATCH   8192
#define NNZ     2400000
#define HALF    (NNZ / 2)
#define TILE    1024                       // elements per scan tile
#define SBLK    ((NTOT + TILE - 1) / TILE) // 147 scan blocks
#define NQ      (3 * BATCH)                // query rows (user, item_i, item_j)

// Static device scratch (no allocation allowed).
__device__ float g_A[(size_t)NTOT * EMBED];   // ping
__device__ float g_B[(size_t)NTOT * EMBED];   // pong
__device__ float g_Sq[(size_t)NQ * EMBED];    // per-query running light_out sum
__device__ int   g_cnt[NTOT + 1];
__device__ int   g_rs[NTOT + 1];              // CSR row starts
__device__ int   g_cur[NTOT];                 // scatter cursors
__device__ int   g_part[SBLK + 1];            // per-tile partial sums
__device__ int2  g_edge[NNZ];                 // packed (dst, val-bits), grouped by src

__device__ __forceinline__ float* pickAB(int sel) { return sel ? g_B : g_A; }

static const size_t N4 = (size_t)NTOT * EMBED / 4;

// Map query slot q (0..NQ) -> node id.
__device__ __forceinline__ int qnode(unsigned int q, const int* __restrict__ user,
                                     const int* __restrict__ item_i,
                                     const int* __restrict__ item_j) {
    unsigned int which = q / BATCH;
    unsigned int b = q % BATCH;
    if (which == 0) return user[b];
    if (which == 1) return item_i[b] + N_USERS;
    return item_j[b] + N_USERS;
}

// A = concat(embed_user_0, embed_item_0); zero g_cnt and the reg_loss slot.
__global__ void k_init(const float* __restrict__ eu, const float* __restrict__ ei,
                       float* __restrict__ out) {
    size_t i = (size_t)blockIdx.x * blockDim.x + threadIdx.x;
    const size_t total = (size_t)NTOT * EMBED / 4;
    if (i >= total) return;
    const size_t userQ = (size_t)N_USERS * EMBED / 4;
    float4 v;
    if (i < userQ) v = reinterpret_cast<const float4*>(eu)[i];
    else           v = reinterpret_cast<const float4*>(ei)[i - userQ];
    reinterpret_cast<float4*>(g_A)[i] = v;
    if (i <= NTOT) g_cnt[i] = 0;
    if (i == 0) out[2 * BATCH] = 0.0f;
}

// Histogram using the mirrored structure: one thread per undirected edge
// increments both endpoint counters (edge appears as (u->it) and (it->u)).
__global__ void k_hist(const int* __restrict__ src, const int* __restrict__ dst) {
    unsigned int i = blockIdx.x * blockDim.x + threadIdx.x;
    if (i >= HALF) return;
    int s = src[i];
    int d = dst[i];
    atomicAdd(&g_cnt[s], 1);
    atomicAdd(&g_cnt[d], 1);
}

// ---- Parallel exclusive scan of g_cnt[0..NTOT) -> g_rs, g_cur ----
__global__ void k_scanA() {
    int b = blockIdx.x;
    int t = threadIdx.x;                 // 256 threads, 4 elems each
    int base = b * TILE + t * 4;
    int s = 0;
    #pragma unroll
    for (int j = 0; j < 4; j++) {
        int idx = base + j;
        if (idx < NTOT) s += g_cnt[idx];
    }
    #pragma unroll
    for (int o = 16; o; o >>= 1) s += __shfl_xor_sync(0xffffffffu, s, o);
    __shared__ int sh[8];
    if ((t & 31) == 0) sh[t >> 5] = s;
    __syncthreads();
    if (t == 0) {
        int tot = 0;
        #pragma unroll
        for (int k = 0; k < 8; k++) tot += sh[k];
        g_part[b] = tot;
    }
}

__global__ void k_scanB() {
    __shared__ int sp[256];
    int t = threadIdx.x;
    sp[t] = (t < SBLK) ? g_part[t] : 0;
    __syncthreads();
    #pragma unroll
    for (int o = 1; o < 256; o <<= 1) {
        int v = (t >= o) ? sp[t - o] : 0;
        __syncthreads();
        sp[t] += v;
        __syncthreads();
    }
    if (t < SBLK) g_part[t] = (t == 0) ? 0 : sp[t - 1];   // exclusive
    if (t == 0) g_rs[NTOT] = NNZ;
}

__global__ void k_scanC() {
    __shared__ int sh[256];
    int b = blockIdx.x;
    int t = threadIdx.x;
    int base = b * TILE + t * 4;
    int c[4];
    int s = 0;
    #pragma unroll
    for (int j = 0; j < 4; j++) {
        int idx = base + j;
        c[j] = (idx < NTOT) ? g_cnt[idx] : 0;
        s += c[j];
    }
    sh[t] = s;
    __syncthreads();
    #pragma unroll
    for (int o = 1; o < 256; o <<= 1) {
        int v = (t >= o) ? sh[t - o] : 0;
        __syncthreads();
        sh[t] += v;
        __syncthreads();
    }
    int run = g_part[b] + ((t == 0) ? 0 : sh[t - 1]);
    #pragma unroll
    for (int j = 0; j < 4; j++) {
        int idx = base + j;
        if (idx < NTOT) { g_rs[idx] = run; g_cur[idx] = run; }
        run += c[j];
    }
}

// Reorder using the mirrored structure: one thread per undirected edge inserts
// both directed records, reusing the (s, d, v) loads.
__global__ void k_reorder(const int* __restrict__ src, const int* __restrict__ dst,
                          const float* __restrict__ vals) {
    unsigned int i = blockIdx.x * blockDim.x + threadIdx.x;
    if (i >= HALF) return;
    int s = src[i];
    int d = dst[i];
    int vb = __float_as_int(vals[i]);
    int p1 = atomicAdd(&g_cur[s], 1);
    g_edge[p1] = make_int2(d, vb);
    int p2 = atomicAdd(&g_cur[d], 1);
    g_edge[p2] = make_int2(s, vb);
}

// One warp per node, MLP-8 pipelined full-table gather (inSel -> inSel^1).
__global__ void k_gather(int inSel) {
    unsigned int gw = (blockIdx.x * blockDim.x + threadIdx.x) >> 5;
    if (gw >= NTOT) return;
    unsigned int lane = threadIdx.x & 31u;
    const float2* __restrict__ in = reinterpret_cast<const float2*>(pickAB(inSel));
    int beg = g_rs[gw];
    int end = g_rs[gw + 1];
    float ax = 0.0f, ay = 0.0f;
    for (int base = beg; base < end; base += 32) {
        int n = end - base; if (n > 32) n = 32;
        int2 ed = make_int2(0, 0);                       // pad: row 0, weight 0
        if (base + (int)lane < end) ed = __ldg(&g_edge[base + lane]);
        for (int k = 0; k < n; k += 8) {
            float2 x[8];
            float  v[8];
            #pragma unroll
            for (int j = 0; j < 8; j++) {
                int idx = k + j;
                int d  = __shfl_sync(0xffffffffu, ed.x, idx & 31);
                int vb = __shfl_sync(0xffffffffu, ed.y, idx & 31);
                v[j] = (idx < n) ? __int_as_float(vb) : 0.0f;
                x[j] = in[(size_t)d * (EMBED / 2) + lane];
            }
            #pragma unroll
            for (int j = 0; j < 8; j++) {
                ax = fmaf(v[j], x[j].x, ax);
                ay = fmaf(v[j], x[j].y, ay);
            }
        }
    }
    size_t idx = (size_t)gw * (EMBED / 2) + lane;
    reinterpret_cast<float2*>(pickAB(inSel ^ 1))[idx] = make_float2(ax, ay);
}

// S_q (set or +=) from a full table at the queried rows. add=0: store, 1: accumulate.
__global__ void k_qacc(const int* __restrict__ user, const int* __restrict__ item_i,
                       const int* __restrict__ item_j, int sel, int add) {
    unsigned int gw = (blockIdx.x * blockDim.x + threadIdx.x) >> 5;
    if (gw >= NQ) return;
    unsigned int lane = threadIdx.x & 31u;
    int node = qnode(gw, user, item_i, item_j);
    float2 v = reinterpret_cast<const float2*>(pickAB(sel))[(size_t)node * (EMBED / 2) + lane];
    float2* sq = reinterpret_cast<float2*>(g_Sq) + (size_t)gw * (EMBED / 2) + lane;
    if (add) {
        float2 s = *sq;
        v.x += s.x; v.y += s.y;
    }
    *sq = v;
}

// Layer 3 restricted to queried rows: S_q[q] += sum_{e in row(node_q)} val_e * in[dst_e].
__global__ void k_qgather(const int* __restrict__ user, const int* __restrict__ item_i,
                          const int* __restrict__ item_j, int inSel) {
    unsigned int gw = (blockIdx.x * blockDim.x + threadIdx.x) >> 5;
    if (gw >= NQ) return;
    unsigned int lane = threadIdx.x & 31u;
    const float2* __restrict__ in = reinterpret_cast<const float2*>(pickAB(inSel));
    int node = qnode(gw, user, item_i, item_j);
    int beg = g_rs[node];
    int end = g_rs[node + 1];
    float ax = 0.0f, ay = 0.0f;
    for (int base = beg; base < end; base += 32) {
        int n = end - base; if (n > 32) n = 32;
        int2 ed = make_int2(0, 0);
        if (base + (int)lane < end) ed = __ldg(&g_edge[base + lane]);
        for (int k = 0; k < n; k += 8) {
            float2 x[8];
            float  v[8];
            #pragma unroll
            for (int j = 0; j < 8; j++) {
                int idx = k + j;
                int d  = __shfl_sync(0xffffffffu, ed.x, idx & 31);
                int vb = __shfl_sync(0xffffffffu, ed.y, idx & 31);
                v[j] = (idx < n) ? __int_as_float(vb) : 0.0f;
                x[j] = in[(size_t)d * (EMBED / 2) + lane];
            }
            #pragma unroll
            for (int j = 0; j < 8; j++) {
                ax = fmaf(v[j], x[j].x, ax);
                ay = fmaf(v[j], x[j].y, ay);
            }
        }
    }
    float2* sq = reinterpret_cast<float2*>(g_Sq) + (size_t)gw * (EMBED / 2) + lane;
    float2 s = *sq;
    *sq = make_float2(s.x + ax, s.y + ay);
}

// Predictions from S_q: pred_i[b] = dot(Sq[b], Sq[BATCH+b]) / 16, same for j.
__global__ void k_pred(float* __restrict__ out) {
    unsigned int gw = (blockIdx.x * blockDim.x + threadIdx.x) >> 5;
    unsigned int lane = threadIdx.x & 31u;
    if (gw >= BATCH) return;
    const float2* sq = reinterpret_cast<const float2*>(g_Sq);
    float2 ue = sq[(size_t)gw * (EMBED / 2) + lane];
    float2 ie = sq[(size_t)(BATCH + gw) * (EMBED / 2) + lane];
    float2 je = sq[(size_t)(2 * BATCH + gw) * (EMBED / 2) + lane];
    float di = ue.x * ie.x + ue.y * ie.y;
    float dj = ue.x * je.x + ue.y * je.y;
    #pragma unroll
    for (int o = 16; o; o >>= 1) {
        di += __shfl_xor_sync(0xffffffffu, di, o);
        dj += __shfl_xor_sync(0xffffffffu, dj, o);
    }
    if (lane == 0) {
        out[gw]         = di * 0.0625f;   // (1/4)*(1/4)
        out[BATCH + gw] = dj * 0.0625f;
    }
}

// reg_loss = 0.5 * (sum u0^2 + sum i0^2 + sum j0^2) / BATCH
__global__ void k_reg(const int* __restrict__ user, const int* __restrict__ item_i,
                      const int* __restrict__ item_j,
                      const float* __restrict__ eu, const float* __restrict__ ei,
                      float* __restrict__ out) {
    unsigned int gw = (blockIdx.x * blockDim.x + threadIdx.x) >> 5;
    unsigned int lane = threadIdx.x & 31u;
    float s = 0.0f;
    if (gw < NQ) {
        unsigned int which = gw / BATCH;
        unsigned int b = gw % BATCH;
        const float* row;
        if (which == 0)      row = eu + (size_t)user[b]   * EMBED;
        else if (which == 1) row = ei + (size_t)item_i[b] * EMBED;
        else                 row = ei + (size_t)item_j[b] * EMBED;
        float2 v = reinterpret_cast<const float2*>(row)[lane];
        s = v.x * v.x + v.y * v.y;
    }
    #pragma unroll
    for (int o = 16; o; o >>= 1) s += __shfl_xor_sync(0xffffffffu, s, o);
    __shared__ float sh[8];
    unsigned int w = threadIdx.x >> 5;
    if (lane == 0) sh[w] = s;
    __syncthreads();
    if (threadIdx.x == 0) {
        float t = 0.0f;
        #pragma unroll
        for (int k = 0; k < 8; k++) t += sh[k];
        atomicAdd(out + 2 * BATCH, t * (0.5f / (float)BATCH));
    }
}

extern "C" void kernel_launch(void* const* d_in, const int* in_sizes, int n_in,
                              void* d_out, int out_size) {
    const int*   user   = (const int*)d_in[0];
    const int*   item_i = (const int*)d_in[1];
    const int*   item_j = (const int*)d_in[2];
    const int*   esrc   = (const int*)d_in[5];
    const int*   edst   = (const int*)d_in[6];
    const float* evals  = (const float*)d_in[7];
    const float* eu     = (const float*)d_in[8];
    const float* ei     = (const float*)d_in[9];
    float* out = (float*)d_out;

    const int gb = (int)((N4 + 255) / 256);          // table-wide float4 kernels
    const int hb = (HALF + 255) / 256;               // per-undirected-edge kernels
    const int wb = (NTOT * 32 + 255) / 256;          // warp-per-node gather
    const int qb = (NQ * 32 + 255) / 256;            // warp-per-query kernels

    k_init<<<gb, 256>>>(eu, ei, out);

    // Build CSR (by src) fresh each launch — mirrored-edge build.
    k_hist<<<hb, 256>>>(esrc, edst);
    k_scanA<<<SBLK, 256>>>();
    k_scanB<<<1, 256>>>();
    k_scanC<<<SBLK, 256>>>();
    k_reorder<<<hb, 256>>>(esrc, edst, evals);

    // S_q = A0 at queried rows.
    k_qacc<<<qb, 256>>>(user, item_i, item_j, 0, 0);

    // Layer 1: A -> B ; S_q += B at queried rows.
    k_gather<<<wb, 256>>>(0);
    k_qacc<<<qb, 256>>>(user, item_i, item_j, 1, 1);

    // Layer 2: B -> A ; S_q += A at queried rows.
    k_gather<<<wb, 256>>>(1);
    k_qacc<<<qb, 256>>>(user, item_i, item_j, 0, 1);

    // Layer 3 only at queried rows: S_q += gather(A).
    k_qgather<<<qb, 256>>>(user, item_i, item_j, 0);

    k_pred<<<(BATCH * 32) / 256, 256>>>(out);
    k_reg<<<qb, 256>>>(user, item_i, item_j, eu, ei, out);
}

// round 13
// speedup vs baseline: 1.4961x; 1.0355x over previous
#include <cuda_runtime.h>
#include <cuda_fp16.h>

#define N_USERS 100000
#define M_ITEMS 50000
#define NTOT    150000
#define EMBED   64
#define BATCH   8192
#define NNZ     2400000
#define HALF_E  (NNZ / 2)
#define TILE    1024                       // elements per scan tile
#define SBLK    ((NTOT + TILE - 1) / TILE) // 147 scan blocks
#define NQ      (3 * BATCH)                // query rows (user, item_i, item_j)

// Static device scratch (no allocation allowed).
__device__ float  g_A[(size_t)NTOT * EMBED];       // fp32 ping (exact S accumulation)
__device__ float  g_B[(size_t)NTOT * EMBED];       // fp32 pong
__device__ __half g_A16[(size_t)NTOT * EMBED];     // fp16 mirror of A (gather input)
__device__ __half g_B16[(size_t)NTOT * EMBED];     // fp16 mirror of B (gather input)
__device__ float  g_Sq[(size_t)NQ * EMBED];        // per-query running light_out sum
__device__ int    g_cnt[NTOT + 1];
__device__ int    g_rs[NTOT + 1];                  // CSR row starts
__device__ int    g_cur[NTOT];                     // scatter cursors
__device__ int    g_part[SBLK + 1];                // per-tile partial sums
__device__ int2   g_edge[NNZ];                     // packed (dst, val-bits), grouped by src

static const size_t N4 = (size_t)NTOT * EMBED / 4;

// Map query slot q (0..NQ) -> node id.
__device__ __forceinline__ int qnode(unsigned int q, const int* __restrict__ user,
                                     const int* __restrict__ item_i,
                                     const int* __restrict__ item_j) {
    unsigned int which = q / BATCH;
    unsigned int b = q % BATCH;
    if (which == 0) return user[b];
    if (which == 1) return item_i[b] + N_USERS;
    return item_j[b] + N_USERS;
}

// A = A16 = concat(embed_user_0, embed_item_0); zero g_cnt and the reg_loss slot.
__global__ void k_init(const float* __restrict__ eu, const float* __restrict__ ei,
                       float* __restrict__ out) {
    size_t i = (size_t)blockIdx.x * blockDim.x + threadIdx.x;
    const size_t total = (size_t)NTOT * EMBED / 4;
    if (i >= total) return;
    const size_t userQ = (size_t)N_USERS * EMBED / 4;
    float4 v;
    if (i < userQ) v = reinterpret_cast<const float4*>(eu)[i];
    else           v = reinterpret_cast<const float4*>(ei)[i - userQ];
    reinterpret_cast<float4*>(g_A)[i] = v;
    __half2* a16 = reinterpret_cast<__half2*>(g_A16);
    a16[2 * i]     = __float22half2_rn(make_float2(v.x, v.y));
    a16[2 * i + 1] = __float22half2_rn(make_float2(v.z, v.w));
    if (i <= NTOT) g_cnt[i] = 0;
    if (i == 0) out[2 * BATCH] = 0.0f;
}

// Histogram using the mirrored structure: one thread per undirected edge.
__global__ void k_hist(const int* __restrict__ src, const int* __restrict__ dst) {
    unsigned int i = blockIdx.x * blockDim.x + threadIdx.x;
    if (i >= HALF_E) return;
    int s = src[i];
    int d = dst[i];
    atomicAdd(&g_cnt[s], 1);
    atomicAdd(&g_cnt[d], 1);
}

// ---- Parallel exclusive scan of g_cnt[0..NTOT) -> g_rs, g_cur ----
__global__ void k_scanA() {
    int b = blockIdx.x;
    int t = threadIdx.x;                 // 256 threads, 4 elems each
    int base = b * TILE + t * 4;
    int s = 0;
    #pragma unroll
    for (int j = 0; j < 4; j++) {
        int idx = base + j;
        if (idx < NTOT) s += g_cnt[idx];
    }
    #pragma unroll
    for (int o = 16; o; o >>= 1) s += __shfl_xor_sync(0xffffffffu, s, o);
    __shared__ int sh[8];
    if ((t & 31) == 0) sh[t >> 5] = s;
    __syncthreads();
    if (t == 0) {
        int tot = 0;
        #pragma unroll
        for (int k = 0; k < 8; k++) tot += sh[k];
        g_part[b] = tot;
    }
}

__global__ void k_scanB() {
    __shared__ int sp[256];
    int t = threadIdx.x;
    sp[t] = (t < SBLK) ? g_part[t] : 0;
    __syncthreads();
    #pragma unroll
    for (int o = 1; o < 256; o <<= 1) {
        int v = (t >= o) ? sp[t - o] : 0;
        __syncthreads();
        sp[t] += v;
        __syncthreads();
    }
    if (t < SBLK) g_part[t] = (t == 0) ? 0 : sp[t - 1];   // exclusive
    if (t == 0) g_rs[NTOT] = NNZ;
}

__global__ void k_scanC() {
    __shared__ int sh[256];
    int b = blockIdx.x;
    int t = threadIdx.x;
    int base = b * TILE + t * 4;
    int c[4];
    int s = 0;
    #pragma unroll
    for (int j = 0; j < 4; j++) {
        int idx = base + j;
        c[j] = (idx < NTOT) ? g_cnt[idx] : 0;
        s += c[j];
    }
    sh[t] = s;
    __syncthreads();
    #pragma unroll
    for (int o = 1; o < 256; o <<= 1) {
        int v = (t >= o) ? sh[t - o] : 0;
        __syncthreads();
        sh[t] += v;
        __syncthreads();
    }
    int run = g_part[b] + ((t == 0) ? 0 : sh[t - 1]);
    #pragma unroll
    for (int j = 0; j < 4; j++) {
        int idx = base + j;
        if (idx < NTOT) { g_rs[idx] = run; g_cur[idx] = run; }
        run += c[j];
    }
}

// Reorder using the mirrored structure: one thread per undirected edge inserts both records.
__global__ void k_reorder(const int* __restrict__ src, const int* __restrict__ dst,
                          const float* __restrict__ vals) {
    unsigned int i = blockIdx.x * blockDim.x + threadIdx.x;
    if (i >= HALF_E) return;
    int s = src[i];
    int d = dst[i];
    int vb = __float_as_int(vals[i]);
    int p1 = atomicAdd(&g_cur[s], 1);
    g_edge[p1] = make_int2(d, vb);
    int p2 = atomicAdd(&g_cur[d], 1);
    g_edge[p2] = make_int2(s, vb);
}

// One warp per node, MLP-8 gather from an fp16 table (128B rows, 1 line each);
// fp32 accumulate; dual-write fp32 (for exact S_q) + fp16 (next layer's input).
// mode 0: A16 -> (B, B16) ; mode 1: B16 -> (A, A16).
__global__ void k_gather(int mode) {
    unsigned int gw = (blockIdx.x * blockDim.x + threadIdx.x) >> 5;
    if (gw >= NTOT) return;
    unsigned int lane = threadIdx.x & 31u;
    const __half2* __restrict__ in = reinterpret_cast<const __half2*>(mode ? g_B16 : g_A16);
    int beg = g_rs[gw];
    int end = g_rs[gw + 1];
    float ax = 0.0f, ay = 0.0f;
    for (int base = beg; base < end; base += 32) {
        int n = end - base; if (n > 32) n = 32;
        int2 ed = make_int2(0, 0);                       // pad: row 0, weight 0
        if (base + (int)lane < end) ed = __ldg(&g_edge[base + lane]);
        for (int k = 0; k < n; k += 8) {
            __half2 h[8];
            float   v[8];
            #pragma unroll
            for (int j = 0; j < 8; j++) {
                int idx = k + j;
                int d  = __shfl_sync(0xffffffffu, ed.x, idx & 31);
                int vb = __shfl_sync(0xffffffffu, ed.y, idx & 31);
                v[j] = (idx < n) ? __int_as_float(vb) : 0.0f;
                h[j] = in[(size_t)d * (EMBED / 2) + lane];   // 8 x 4B loads in flight
            }
            #pragma unroll
            for (int j = 0; j < 8; j++) {
                float2 x = __half22float2(h[j]);
                ax = fmaf(v[j], x.x, ax);
                ay = fmaf(v[j], x.y, ay);
            }
        }
    }
    size_t idx = (size_t)gw * (EMBED / 2) + lane;
    float*  out32 = mode ? g_A   : g_B;
    __half* out16 = mode ? g_A16 : g_B16;
    reinterpret_cast<float2*>(out32)[idx] = make_float2(ax, ay);
    reinterpret_cast<__half2*>(out16)[idx] = __float22half2_rn(make_float2(ax, ay));
}

// S_q (set or +=) from an fp32 table at the queried rows. add=0: store, 1: accumulate.
__global__ void k_qacc(const int* __restrict__ user, const int* __restrict__ item_i,
                       const int* __restrict__ item_j, int sel, int add) {
    unsigned int gw = (blockIdx.x * blockDim.x + threadIdx.x) >> 5;
    if (gw >= NQ) return;
    unsigned int lane = threadIdx.x & 31u;
    int node = qnode(gw, user, item_i, item_j);
    const float* tab = sel ? g_B : g_A;
    float2 v = reinterpret_cast<const float2*>(tab)[(size_t)node * (EMBED / 2) + lane];
    float2* sq = reinterpret_cast<float2*>(g_Sq) + (size_t)gw * (EMBED / 2) + lane;
    if (add) {
        float2 s = *sq;
        v.x += s.x; v.y += s.y;
    }
    *sq = v;
}

// Layer 3 restricted to queried rows: S_q[q] += sum val_e * A16[dst_e] (fp32 accum).
__global__ void k_qgather(const int* __restrict__ user, const int* __restrict__ item_i,
                          const int* __restrict__ item_j) {
    unsigned int gw = (blockIdx.x * blockDim.x + threadIdx.x) >> 5;
    if (gw >= NQ) return;
    unsigned int lane = threadIdx.x & 31u;
    const __half2* __restrict__ in = reinterpret_cast<const __half2*>(g_A16);
    int node = qnode(gw, user, item_i, item_j);
    int beg = g_rs[node];
    int end = g_rs[node + 1];
    float ax = 0.0f, ay = 0.0f;
    for (int base = beg; base < end; base += 32) {
        int n = end - base; if (n > 32) n = 32;
        int2 ed = make_int2(0, 0);
        if (base + (int)lane < end) ed = __ldg(&g_edge[base + lane]);
        for (int k = 0; k < n; k += 8) {
            __half2 h[8];
            float   v[8];
            #pragma unroll
            for (int j = 0; j < 8; j++) {
                int idx = k + j;
                int d  = __shfl_sync(0xffffffffu, ed.x, idx & 31);
                int vb = __shfl_sync(0xffffffffu, ed.y, idx & 31);
                v[j] = (idx < n) ? __int_as_float(vb) : 0.0f;
                h[j] = in[(size_t)d * (EMBED / 2) + lane];
            }
            #pragma unroll
            for (int j = 0; j < 8; j++) {
                float2 x = __half22float2(h[j]);
                ax = fmaf(v[j], x.x, ax);
                ay = fmaf(v[j], x.y, ay);
            }
        }
    }
    float2* sq = reinterpret_cast<float2*>(g_Sq) + (size_t)gw * (EMBED / 2) + lane;
    float2 s = *sq;
    *sq = make_float2(s.x + ax, s.y + ay);
}

// Predictions from S_q: pred_i[b] = dot(Sq[b], Sq[BATCH+b]) / 16, same for j.
__global__ void k_pred(float* __restrict__ out) {
    unsigned int gw = (blockIdx.x * blockDim.x + threadIdx.x) >> 5;
    unsigned int lane = threadIdx.x & 31u;
    if (gw >= BATCH) return;
    const float2* sq = reinterpret_cast<const float2*>(g_Sq);
    float2 ue = sq[(size_t)gw * (EMBED / 2) + lane];
    float2 ie = sq[(size_t)(BATCH + gw) * (EMBED / 2) + lane];
    float2 je = sq[(size_t)(2 * BATCH + gw) * (EMBED / 2) + lane];
    float di = ue.x * ie.x + ue.y * ie.y;
    float dj = ue.x * je.x + ue.y * je.y;
    #pragma unroll
    for (int o = 16; o; o >>= 1) {
        di += __shfl_xor_sync(0xffffffffu, di, o);
        dj += __shfl_xor_sync(0xffffffffu, dj, o);
    }
    if (lane == 0) {
        out[gw]         = di * 0.0625f;   // (1/4)*(1/4)
        out[BATCH + gw] = dj * 0.0625f;
    }
}

// reg_loss = 0.5 * (sum u0^2 + sum i0^2 + sum j0^2) / BATCH
__global__ void k_reg(const int* __restrict__ user, const int* __restrict__ item_i,
                      const int* __restrict__ item_j,
                      const float* __restrict__ eu, const float* __restrict__ ei,
                      float* __restrict__ out) {
    unsigned int gw = (blockIdx.x * blockDim.x + threadIdx.x) >> 5;
    unsigned int lane = threadIdx.x & 31u;
    float s = 0.0f;
    if (gw < NQ) {
        unsigned int which = gw / BATCH;
        unsigned int b = gw % BATCH;
        const float* row;
        if (which == 0)      row = eu + (size_t)user[b]   * EMBED;
        else if (which == 1) row = ei + (size_t)item_i[b] * EMBED;
        else                 row = ei + (size_t)item_j[b] * EMBED;
        float2 v = reinterpret_cast<const float2*>(row)[lane];
        s = v.x * v.x + v.y * v.y;
    }
    #pragma unroll
    for (int o = 16; o; o >>= 1) s += __shfl_xor_sync(0xffffffffu, s, o);
    __shared__ float sh[8];
    unsigned int w = threadIdx.x >> 5;
    if (lane == 0) sh[w] = s;
    __syncthreads();
    if (threadIdx.x == 0) {
        float t = 0.0f;
        #pragma unroll
        for (int k = 0; k < 8; k++) t += sh[k];
        atomicAdd(out + 2 * BATCH, t * (0.5f / (float)BATCH));
    }
}

extern "C" void kernel_launch(void* const* d_in, const int* in_sizes, int n_in,
                              void* d_out, int out_size) {
    const int*   user   = (const int*)d_in[0];
    const int*   item_i = (const int*)d_in[1];
    const int*   item_j = (const int*)d_in[2];
    const int*   esrc   = (const int*)d_in[5];
    const int*   edst   = (const int*)d_in[6];
    const float* evals  = (const float*)d_in[7];
    const float* eu     = (const float*)d_in[8];
    const float* ei     = (const float*)d_in[9];
    float* out = (float*)d_out;

    const int gb = (int)((N4 + 255) / 256);          // table-wide float4 kernels
    const int hb = (HALF_E + 255) / 256;             // per-undirected-edge kernels
    const int wb = (NTOT * 32 + 255) / 256;          // warp-per-node gather
    const int qb = (NQ * 32 + 255) / 256;            // warp-per-query kernels

    k_init<<<gb, 256>>>(eu, ei, out);

    // Build CSR (by src) fresh each launch — mirrored-edge build.
    k_hist<<<hb, 256>>>(esrc, edst);
    k_scanA<<<SBLK, 256>>>();
    k_scanB<<<1, 256>>>();
    k_scanC<<<SBLK, 256>>>();
    k_reorder<<<hb, 256>>>(esrc, edst, evals);

    // S_q = A0 (fp32) at queried rows.
    k_qacc<<<qb, 256>>>(user, item_i, item_j, 0, 0);

    // Layer 1: A16 -> (B, B16) ; S_q += B (fp32) at queried rows.
    k_gather<<<wb, 256>>>(0);
    k_qacc<<<qb, 256>>>(user, item_i, item_j, 1, 1);

    // Layer 2: B16 -> (A, A16) ; S_q += A (fp32) at queried rows.
    k_gather<<<wb, 256>>>(1);
    k_qacc<<<qb, 256>>>(user, item_i, item_j, 0, 1);

    // Layer 3 only at queried rows: S_q += gather(A16).
    k_qgather<<<qb, 256>>>(user, item_i, item_j);

    k_pred<<<(BATCH * 32) / 256, 256>>>(out);
    k_reg<<<qb, 256>>>(user, item_i, item_j, eu, ei, out);
}

// round 14
// speedup vs baseline: 1.6220x; 1.0842x over previous
#include <cuda_runtime.h>
#include <cuda_fp16.h>

#define N_USERS 100000
#define M_ITEMS 50000
#define NTOT    150000
#define EMBED   64
#define BATCH   8192
#define NNZ     2400000
#define HALF_E  (NNZ / 2)
#define TILE    1024                       // elements per scan tile
#define SBLK    ((NTOT + TILE - 1) / TILE) // 147 scan blocks (<= 148 SMs: co-resident)
#define NQ      (3 * BATCH)                // query rows (user, item_i, item_j)

// Static device scratch (no allocation allowed).
__device__ __half g_A16[(size_t)NTOT * EMBED];     // fp16 ping
__device__ __half g_B16[(size_t)NTOT * EMBED];     // fp16 pong
__device__ float  g_Sq[(size_t)NQ * EMBED];        // per-query running light_out sum (fp32)
__device__ int    g_cnt[NTOT + 1];
__device__ int    g_rs[NTOT + 1];                  // CSR row starts
__device__ int    g_cur[NTOT];                     // scatter cursors
__device__ int    g_part[SBLK + 1];                // per-tile totals
__device__ int    g_sync;                          // grid barrier counter for k_scan
__device__ int2   g_edge[NNZ];                     // packed (dst, val-bits), grouped by src

static const size_t N4 = (size_t)NTOT * EMBED / 4;

// Map query slot q (0..NQ) -> node id.
__device__ __forceinline__ int qnode(unsigned int q, const int* __restrict__ user,
                                     const int* __restrict__ item_i,
                                     const int* __restrict__ item_j) {
    unsigned int which = q / BATCH;
    unsigned int b = q % BATCH;
    if (which == 0) return user[b];
    if (which == 1) return item_i[b] + N_USERS;
    return item_j[b] + N_USERS;
}

// A16 = fp16(concat(embed_user_0, embed_item_0)); zero g_cnt, g_sync, reg_loss slot.
__global__ void k_init(const float* __restrict__ eu, const float* __restrict__ ei,
                       float* __restrict__ out) {
    size_t i = (size_t)blockIdx.x * blockDim.x + threadIdx.x;
    const size_t total = (size_t)NTOT * EMBED / 4;
    if (i >= total) return;
    const size_t userQ = (size_t)N_USERS * EMBED / 4;
    float4 v;
    if (i < userQ) v = reinterpret_cast<const float4*>(eu)[i];
    else           v = reinterpret_cast<const float4*>(ei)[i - userQ];
    __half2* a16 = reinterpret_cast<__half2*>(g_A16);
    a16[2 * i]     = __float22half2_rn(make_float2(v.x, v.y));
    a16[2 * i + 1] = __float22half2_rn(make_float2(v.z, v.w));
    if (i <= NTOT) g_cnt[i] = 0;
    if (i == 0) { out[2 * BATCH] = 0.0f; g_sync = 0; }
}

// Fused: S_q = emb0 row at each query slot (fp32) AND reg_loss accumulation.
__global__ void k_regq(const int* __restrict__ user, const int* __restrict__ item_i,
                       const int* __restrict__ item_j,
                       const float* __restrict__ eu, const float* __restrict__ ei,
                       float* __restrict__ out) {
    unsigned int gw = (blockIdx.x * blockDim.x + threadIdx.x) >> 5;
    unsigned int lane = threadIdx.x & 31u;
    float s = 0.0f;
    if (gw < NQ) {
        int node = qnode(gw, user, item_i, item_j);
        const float2* row = (node < N_USERS)
            ? reinterpret_cast<const float2*>(eu + (size_t)node * EMBED)
            : reinterpret_cast<const float2*>(ei + (size_t)(node - N_USERS) * EMBED);
        float2 v = row[lane];
        reinterpret_cast<float2*>(g_Sq)[(size_t)gw * (EMBED / 2) + lane] = v;
        s = v.x * v.x + v.y * v.y;
    }
    #pragma unroll
    for (int o = 16; o; o >>= 1) s += __shfl_xor_sync(0xffffffffu, s, o);
    __shared__ float sh[8];
    unsigned int w = threadIdx.x >> 5;
    if (lane == 0) sh[w] = s;
    __syncthreads();
    if (threadIdx.x == 0) {
        float t = 0.0f;
        #pragma unroll
        for (int k = 0; k < 8; k++) t += sh[k];
        atomicAdd(out + 2 * BATCH, t * (0.5f / (float)BATCH));
    }
}

// Histogram using the mirrored structure: one thread per undirected edge.
__global__ void k_hist(const int* __restrict__ src, const int* __restrict__ dst) {
    unsigned int i = blockIdx.x * blockDim.x + threadIdx.x;
    if (i >= HALF_E) return;
    int s = src[i];
    int d = dst[i];
    atomicAdd(&g_cnt[s], 1);
    atomicAdd(&g_cnt[d], 1);
}

// Fused single-kernel exclusive scan of g_cnt -> g_rs, g_cur.
// 147 blocks (all co-resident on 148 SMs) with an atomic-counter grid barrier.
__global__ void k_scan() {
    __shared__ int sh[256];
    __shared__ int sp[256];
    int b = blockIdx.x;
    int t = threadIdx.x;
    int base = b * TILE + t * 4;
    int c[4];
    int s = 0;
    #pragma unroll
    for (int j = 0; j < 4; j++) {
        int idx = base + j;
        c[j] = (idx < NTOT) ? g_cnt[idx] : 0;
        s += c[j];
    }
    sh[t] = s;
    __syncthreads();
    // Inclusive block scan of per-thread sums.
    #pragma unroll
    for (int o = 1; o < 256; o <<= 1) {
        int v = (t >= o) ? sh[t - o] : 0;
        __syncthreads();
        sh[t] += v;
        __syncthreads();
    }
    // Publish block total, then grid barrier.
    if (t == 255) g_part[b] = sh[255];
    __threadfence();
    __syncthreads();
    if (t == 0) {
        atomicAdd(&g_sync, 1);
        while (atomicAdd(&g_sync, 0) < gridDim.x) { }
    }
    __syncthreads();
    // off = sum of totals of blocks before b (parallel reduction).
    sp[t] = (t < b && t < SBLK) ? g_part[t] : 0;
    __syncthreads();
    #pragma unroll
    for (int o = 128; o; o >>= 1) {
        if (t < o) sp[t] += sp[t + o];
        __syncthreads();
    }
    int run = sp[0] + sh[t] - s;   // block offset + exclusive within block
    #pragma unroll
    for (int j = 0; j < 4; j++) {
        int idx = base + j;
        if (idx < NTOT) { g_rs[idx] = run; g_cur[idx] = run; }
        run += c[j];
    }
    if (b == 0 && t == 0) g_rs[NTOT] = NNZ;
}

// Reorder using the mirrored structure: one thread per undirected edge inserts both records.
__global__ void k_reorder(const int* __restrict__ src, const int* __restrict__ dst,
                          const float* __restrict__ vals) {
    unsigned int i = blockIdx.x * blockDim.x + threadIdx.x;
    if (i >= HALF_E) return;
    int s = src[i];
    int d = dst[i];
    int vb = __float_as_int(vals[i]);
    int p1 = atomicAdd(&g_cur[s], 1);
    g_edge[p1] = make_int2(d, vb);
    int p2 = atomicAdd(&g_cur[d], 1);
    g_edge[p2] = make_int2(s, vb);
}

// One warp per node, MLP-8 gather fp16 -> fp16 (fp32 accumulate).
// mode 0: A16 -> B16 ; mode 1: B16 -> A16.
__global__ void k_gather(int mode) {
    unsigned int gw = (blockIdx.x * blockDim.x + threadIdx.x) >> 5;
    if (gw >= NTOT) return;
    unsigned int lane = threadIdx.x & 31u;
    const __half2* __restrict__ in = reinterpret_cast<const __half2*>(mode ? g_B16 : g_A16);
    int beg = g_rs[gw];
    int end = g_rs[gw + 1];
    float ax = 0.0f, ay = 0.0f;
    for (int base = beg; base < end; base += 32) {
        int n = end - base; if (n > 32) n = 32;
        int2 ed = make_int2(0, 0);                       // pad: row 0, weight 0
        if (base + (int)lane < end) ed = __ldg(&g_edge[base + lane]);
        for (int k = 0; k < n; k += 8) {
            __half2 h[8];
            float   v[8];
            #pragma unroll
            for (int j = 0; j < 8; j++) {
                int idx = k + j;
                int d  = __shfl_sync(0xffffffffu, ed.x, idx & 31);
                int vb = __shfl_sync(0xffffffffu, ed.y, idx & 31);
                v[j] = (idx < n) ? __int_as_float(vb) : 0.0f;
                h[j] = in[(size_t)d * (EMBED / 2) + lane];   // 8 loads in flight
            }
            #pragma unroll
            for (int j = 0; j < 8; j++) {
                float2 x = __half22float2(h[j]);
                ax = fmaf(v[j], x.x, ax);
                ay = fmaf(v[j], x.y, ay);
            }
        }
    }
    size_t idx = (size_t)gw * (EMBED / 2) + lane;
    __half* out16 = mode ? g_A16 : g_B16;
    reinterpret_cast<__half2*>(out16)[idx] = __float22half2_rn(make_float2(ax, ay));
}

// S_q += fp16 table rows at queried slots. sel 1: B16, sel 0: A16.
__global__ void k_qacc(const int* __restrict__ user, const int* __restrict__ item_i,
                       const int* __restrict__ item_j, int sel) {
    unsigned int gw = (blockIdx.x * blockDim.x + threadIdx.x) >> 5;
    if (gw >= NQ) return;
    unsigned int lane = threadIdx.x & 31u;
    int node = qnode(gw, user, item_i, item_j);
    const __half2* tab = reinterpret_cast<const __half2*>(sel ? g_B16 : g_A16);
    float2 v = __half22float2(tab[(size_t)node * (EMBED / 2) + lane]);
    float2* sq = reinterpret_cast<float2*>(g_Sq) + (size_t)gw * (EMBED / 2) + lane;
    float2 s = *sq;
    *sq = make_float2(s.x + v.x, s.y + v.y);
}

// Layer 3 restricted to queried rows: S_q[q] += sum val_e * A16[dst_e] (fp32 accum).
__global__ void k_qgather(const int* __restrict__ user, const int* __restrict__ item_i,
                          const int* __restrict__ item_j) {
    unsigned int gw = (blockIdx.x * blockDim.x + threadIdx.x) >> 5;
    if (gw >= NQ) return;
    unsigned int lane = threadIdx.x & 31u;
    const __half2* __restrict__ in = reinterpret_cast<const __half2*>(g_A16);
    int node = qnode(gw, user, item_i, item_j);
    int beg = g_rs[node];
    int end = g_rs[node + 1];
    float ax = 0.0f, ay = 0.0f;
    for (int base = beg; base < end; base += 32) {
        int n = end - base; if (n > 32) n = 32;
        int2 ed = make_int2(0, 0);
        if (base + (int)lane < end) ed = __ldg(&g_edge[base + lane]);
        for (int k = 0; k < n; k += 8) {
            __half2 h[8];
            float   v[8];
            #pragma unroll
            for (int j = 0; j < 8; j++) {
                int idx = k + j;
                int d  = __shfl_sync(0xffffffffu, ed.x, idx & 31);
                int vb = __shfl_sync(0xffffffffu, ed.y, idx & 31);
                v[j] = (idx < n) ? __int_as_float(vb) : 0.0f;
                h[j] = in[(size_t)d * (EMBED / 2) + lane];
            }
            #pragma unroll
            for (int j = 0; j < 8; j++) {
                float2 x = __half22float2(h[j]);
                ax = fmaf(v[j], x.x, ax);
                ay = fmaf(v[j], x.y, ay);
            }
        }
    }
    float2* sq = reinterpret_cast<float2*>(g_Sq) + (size_t)gw * (EMBED / 2) + lane;
    float2 s = *sq;
    *sq = make_float2(s.x + ax, s.y + ay);
}

// Predictions from S_q: pred_i[b] = dot(Sq[b], Sq[BATCH+b]) / 16, same for j.
__global__ void k_pred(float* __restrict__ out) {
    unsigned int gw = (blockIdx.x * blockDim.x + threadIdx.x) >> 5;
    unsigned int lane = threadIdx.x & 31u;
    if (gw >= BATCH) return;
    const float2* sq = reinterpret_cast<const float2*>(g_Sq);
    float2 ue = sq[(size_t)gw * (EMBED / 2) + lane];
    float2 ie = sq[(size_t)(BATCH + gw) * (EMBED / 2) + lane];
    float2 je = sq[(size_t)(2 * BATCH + gw) * (EMBED / 2) + lane];
    float di = ue.x * ie.x + ue.y * ie.y;
    float dj = ue.x * je.x + ue.y * je.y;
    #pragma unroll
    for (int o = 16; o; o >>= 1) {
        di += __shfl_xor_sync(0xffffffffu, di, o);
        dj += __shfl_xor_sync(0xffffffffu, dj, o);
    }
    if (lane == 0) {
        out[gw]         = di * 0.0625f;   // (1/4)*(1/4)
        out[BATCH + gw] = dj * 0.0625f;
    }
}

extern "C" void kernel_launch(void* const* d_in, const int* in_sizes, int n_in,
                              void* d_out, int out_size) {
    const int*   user   = (const int*)d_in[0];
    const int*   item_i = (const int*)d_in[1];
    const int*   item_j = (const int*)d_in[2];
    const int*   esrc   = (const int*)d_in[5];
    const int*   edst   = (const int*)d_in[6];
    const float* evals  = (const float*)d_in[7];
    const float* eu     = (const float*)d_in[8];
    const float* ei     = (const float*)d_in[9];
    float* out = (float*)d_out;

    const int gb = (int)((N4 + 255) / 256);          // table-wide kernels
    const int hb = (HALF_E + 255) / 256;             // per-undirected-edge kernels
    const int wb = (NTOT * 32 + 255) / 256;          // warp-per-node gather
    const int qb = (NQ * 32 + 255) / 256;            // warp-per-query kernels

    k_init<<<gb, 256>>>(eu, ei, out);                        // 1
    k_regq<<<qb, 256>>>(user, item_i, item_j, eu, ei, out);  // 2: S_q = emb0 rows + reg

    // Build CSR fresh each launch.
    k_hist<<<hb, 256>>>(esrc, edst);                         // 3
    k_scan<<<SBLK, 256>>>();                                 // 4  (ncu capture slot)
    k_reorder<<<hb, 256>>>(esrc, edst, evals);               // 5

    // Layer 1: A16 -> B16 ; S_q += B16 at queried rows.
    k_gather<<<wb, 256>>>(0);                                // 6
    k_qacc<<<qb, 256>>>(user, item_i, item_j, 1);            // 7

    // Layer 2: B16 -> A16 ; S_q += A16 at queried rows.
    k_gather<<<wb, 256>>>(1);                                // 8
    k_qacc<<<qb, 256>>>(user, item_i, item_j, 0);            // 9

    // Layer 3 only at queried rows: S_q += gather(A16).
    k_qgather<<<qb, 256>>>(user, item_i, item_j);            // 10

    k_pred<<<(BATCH * 32) / 256, 256>>>(out);                // 11
}

// round 15
// speedup vs baseline: 1.7853x; 1.1006x over previous
#include <cuda_runtime.h>
#include <cuda_fp16.h>

#define N_USERS 100000
#define M_ITEMS 50000
#define NTOT    150000
#define EMBED   64
#define BATCH   8192
#define NNZ     2400000
#define HALF_E  (NNZ / 2)
#define TILE    1024                       // elements per scan tile
#define SBLK    ((NTOT + TILE - 1) / TILE) // 147 scan blocks (<= 148 SMs: co-resident)
#define NQ      (3 * BATCH)                // query rows (user, item_i, item_j)

// Static device scratch (no allocation allowed).
__device__ __half g_A16[(size_t)NTOT * EMBED];     // fp16 ping
__device__ __half g_B16[(size_t)NTOT * EMBED];     // fp16 pong
__device__ float  g_Sq[(size_t)NQ * EMBED];        // per-query running light_out sum (fp32)
__device__ int    g_cnt[NTOT + 1];
__device__ int    g_rs[NTOT + 1];                  // CSR row starts
__device__ int    g_cur[NTOT];                     // scatter cursors
__device__ int    g_part[SBLK + 1];                // per-tile totals
__device__ int    g_sync;                          // grid barrier counter for k_scan
__device__ int2   g_edge[NNZ];                     // packed (dst, val-bits), grouped by src

static const size_t N4 = (size_t)NTOT * EMBED / 4;

// Map query slot q (0..NQ) -> node id.
__device__ __forceinline__ int qnode(unsigned int q, const int* __restrict__ user,
                                     const int* __restrict__ item_i,
                                     const int* __restrict__ item_j) {
    unsigned int which = q / BATCH;
    unsigned int b = q % BATCH;
    if (which == 0) return user[b];
    if (which == 1) return item_i[b] + N_USERS;
    return item_j[b] + N_USERS;
}

// A16 = fp16(concat(embed_user_0, embed_item_0)); zero g_cnt, g_sync, reg_loss slot.
__global__ void k_init(const float* __restrict__ eu, const float* __restrict__ ei,
                       float* __restrict__ out) {
    size_t i = (size_t)blockIdx.x * blockDim.x + threadIdx.x;
    const size_t total = (size_t)NTOT * EMBED / 4;
    if (i >= total) return;
    const size_t userQ = (size_t)N_USERS * EMBED / 4;
    float4 v;
    if (i < userQ) v = reinterpret_cast<const float4*>(eu)[i];
    else           v = reinterpret_cast<const float4*>(ei)[i - userQ];
    __half2* a16 = reinterpret_cast<__half2*>(g_A16);
    a16[2 * i]     = __float22half2_rn(make_float2(v.x, v.y));
    a16[2 * i + 1] = __float22half2_rn(make_float2(v.z, v.w));
    if (i <= NTOT) g_cnt[i] = 0;
    if (i == 0) { out[2 * BATCH] = 0.0f; g_sync = 0; }
}

// Fused: S_q = emb0 row at each query slot (fp32) AND reg_loss accumulation.
__global__ void k_regq(const int* __restrict__ user, const int* __restrict__ item_i,
                       const int* __restrict__ item_j,
                       const float* __restrict__ eu, const float* __restrict__ ei,
                       float* __restrict__ out) {
    unsigned int gw = (blockIdx.x * blockDim.x + threadIdx.x) >> 5;
    unsigned int lane = threadIdx.x & 31u;
    float s = 0.0f;
    if (gw < NQ) {
        int node = qnode(gw, user, item_i, item_j);
        const float2* row = (node < N_USERS)
            ? reinterpret_cast<const float2*>(eu + (size_t)node * EMBED)
            : reinterpret_cast<const float2*>(ei + (size_t)(node - N_USERS) * EMBED);
        float2 v = row[lane];
        reinterpret_cast<float2*>(g_Sq)[(size_t)gw * (EMBED / 2) + lane] = v;
        s = v.x * v.x + v.y * v.y;
    }
    #pragma unroll
    for (int o = 16; o; o >>= 1) s += __shfl_xor_sync(0xffffffffu, s, o);
    __shared__ float sh[8];
    unsigned int w = threadIdx.x >> 5;
    if (lane == 0) sh[w] = s;
    __syncthreads();
    if (threadIdx.x == 0) {
        float t = 0.0f;
        #pragma unroll
        for (int k = 0; k < 8; k++) t += sh[k];
        atomicAdd(out + 2 * BATCH, t * (0.5f / (float)BATCH));
    }
}

// Histogram using the mirrored structure: one thread per undirected edge.
__global__ void k_hist(const int* __restrict__ src, const int* __restrict__ dst) {
    unsigned int i = blockIdx.x * blockDim.x + threadIdx.x;
    if (i >= HALF_E) return;
    int s = src[i];
    int d = dst[i];
    atomicAdd(&g_cnt[s], 1);
    atomicAdd(&g_cnt[d], 1);
}

// Fused single-kernel exclusive scan of g_cnt -> g_rs, g_cur.
// 147 blocks (all co-resident on 148 SMs) with an atomic-counter grid barrier.
__global__ void k_scan() {
    __shared__ int sh[256];
    __shared__ int sp[256];
    int b = blockIdx.x;
    int t = threadIdx.x;
    int base = b * TILE + t * 4;
    int c[4];
    int s = 0;
    #pragma unroll
    for (int j = 0; j < 4; j++) {
        int idx = base + j;
        c[j] = (idx < NTOT) ? g_cnt[idx] : 0;
        s += c[j];
    }
    sh[t] = s;
    __syncthreads();
    // Inclusive block scan of per-thread sums.
    #pragma unroll
    for (int o = 1; o < 256; o <<= 1) {
        int v = (t >= o) ? sh[t - o] : 0;
        __syncthreads();
        sh[t] += v;
        __syncthreads();
    }
    // Publish block total, then grid barrier.
    if (t == 255) g_part[b] = sh[255];
    __threadfence();
    __syncthreads();
    if (t == 0) {
        atomicAdd(&g_sync, 1);
        while (atomicAdd(&g_sync, 0) < gridDim.x) { }
    }
    __syncthreads();
    // off = sum of totals of blocks before b (parallel reduction).
    sp[t] = (t < b && t < SBLK) ? g_part[t] : 0;
    __syncthreads();
    #pragma unroll
    for (int o = 128; o; o >>= 1) {
        if (t < o) sp[t] += sp[t + o];
        __syncthreads();
    }
    int run = sp[0] + sh[t] - s;   // block offset + exclusive within block
    #pragma unroll
    for (int j = 0; j < 4; j++) {
        int idx = base + j;
        if (idx < NTOT) { g_rs[idx] = run; g_cur[idx] = run; }
        run += c[j];
    }
    if (b == 0 && t == 0) g_rs[NTOT] = NNZ;
}

// Reorder using the mirrored structure: one thread per undirected edge inserts both records.
__global__ void k_reorder(const int* __restrict__ src, const int* __restrict__ dst,
                          const float* __restrict__ vals) {
    unsigned int i = blockIdx.x * blockDim.x + threadIdx.x;
    if (i >= HALF_E) return;
    int s = src[i];
    int d = dst[i];
    int vb = __float_as_int(vals[i]);
    int p1 = atomicAdd(&g_cur[s], 1);
    g_edge[p1] = make_int2(d, vb);
    int p2 = atomicAdd(&g_cur[d], 1);
    g_edge[p2] = make_int2(s, vb);
}

// One warp per node: SHFL-free gather. Every lane uniformly loads the edge
// record (HW broadcast; L1 hit 15/16 of the time), 8 edges unrolled so 8
// independent row loads stay in flight. fp16 rows, fp32 accumulate.
// mode 0: A16 -> B16 ; mode 1: B16 -> A16.
__global__ void k_gather(int mode) {
    unsigned int gw = (blockIdx.x * blockDim.x + threadIdx.x) >> 5;
    if (gw >= NTOT) return;
    unsigned int lane = threadIdx.x & 31u;
    const __half2* __restrict__ in = reinterpret_cast<const __half2*>(mode ? g_B16 : g_A16);
    int e   = g_rs[gw];
    int end = g_rs[gw + 1];
    float ax = 0.0f, ay = 0.0f;
    for (; e + 8 <= end; e += 8) {
        int2   ed[8];
        __half2 h[8];
        #pragma unroll
        for (int j = 0; j < 8; j++) ed[j] = __ldg(&g_edge[e + j]);      // uniform bcast
        #pragma unroll
        for (int j = 0; j < 8; j++) h[j] = in[(size_t)ed[j].x * (EMBED / 2) + lane];
        #pragma unroll
        for (int j = 0; j < 8; j++) {
            float2 x = __half22float2(h[j]);
            float  v = __int_as_float(ed[j].y);
            ax = fmaf(v, x.x, ax);
            ay = fmaf(v, x.y, ay);
        }
    }
    for (; e < end; e++) {
        int2 ed = __ldg(&g_edge[e]);
        float2 x = __half22float2(in[(size_t)ed.x * (EMBED / 2) + lane]);
        float  v = __int_as_float(ed.y);
        ax = fmaf(v, x.x, ax);
        ay = fmaf(v, x.y, ay);
    }
    size_t idx = (size_t)gw * (EMBED / 2) + lane;
    __half* out16 = mode ? g_A16 : g_B16;
    reinterpret_cast<__half2*>(out16)[idx] = __float22half2_rn(make_float2(ax, ay));
}

// S_q += fp16 table rows at queried slots. sel 1: B16, sel 0: A16.
__global__ void k_qacc(const int* __restrict__ user, const int* __restrict__ item_i,
                       const int* __restrict__ item_j, int sel) {
    unsigned int gw = (blockIdx.x * blockDim.x + threadIdx.x) >> 5;
    if (gw >= NQ) return;
    unsigned int lane = threadIdx.x & 31u;
    int node = qnode(gw, user, item_i, item_j);
    const __half2* tab = reinterpret_cast<const __half2*>(sel ? g_B16 : g_A16);
    float2 v = __half22float2(tab[(size_t)node * (EMBED / 2) + lane]);
    float2* sq = reinterpret_cast<float2*>(g_Sq) + (size_t)gw * (EMBED / 2) + lane;
    float2 s = *sq;
    *sq = make_float2(s.x + v.x, s.y + v.y);
}

// Layer 3 restricted to queried rows, SHFL-free: S_q[q] += sum val_e * A16[dst_e].
__global__ void k_qgather(const int* __restrict__ user, const int* __restrict__ item_i,
                          const int* __restrict__ item_j) {
    unsigned int gw = (blockIdx.x * blockDim.x + threadIdx.x) >> 5;
    if (gw >= NQ) return;
    unsigned int lane = threadIdx.x & 31u;
    const __half2* __restrict__ in = reinterpret_cast<const __half2*>(g_A16);
    int node = qnode(gw, user, item_i, item_j);
    int e   = g_rs[node];
    int end = g_rs[node + 1];
    float ax = 0.0f, ay = 0.0f;
    for (; e + 8 <= end; e += 8) {
        int2   ed[8];
        __half2 h[8];
        #pragma unroll
        for (int j = 0; j < 8; j++) ed[j] = __ldg(&g_edge[e + j]);
        #pragma unroll
        for (int j = 0; j < 8; j++) h[j] = in[(size_t)ed[j].x * (EMBED / 2) + lane];
        #pragma unroll
        for (int j = 0; j < 8; j++) {
            float2 x = __half22float2(h[j]);
            float  v = __int_as_float(ed[j].y);
            ax = fmaf(v, x.x, ax);
            ay = fmaf(v, x.y, ay);
        }
    }
    for (; e < end; e++) {
        int2 ed = __ldg(&g_edge[e]);
        float2 x = __half22float2(in[(size_t)ed.x * (EMBED / 2) + lane]);
        float  v = __int_as_float(ed.y);
        ax = fmaf(v, x.x, ax);
        ay = fmaf(v, x.y, ay);
    }
    float2* sq = reinterpret_cast<float2*>(g_Sq) + (size_t)gw * (EMBED / 2) + lane;
    float2 s = *sq;
    *sq = make_float2(s.x + ax, s.y + ay);
}

// Predictions from S_q: pred_i[b] = dot(Sq[b], Sq[BATCH+b]) / 16, same for j.
__global__ void k_pred(float* __restrict__ out) {
    unsigned int gw = (blockIdx.x * blockDim.x + threadIdx.x) >> 5;
    unsigned int lane = threadIdx.x & 31u;
    if (gw >= BATCH) return;
    const float2* sq = reinterpret_cast<const float2*>(g_Sq);
    float2 ue = sq[(size_t)gw * (EMBED / 2) + lane];
    float2 ie = sq[(size_t)(BATCH + gw) * (EMBED / 2) + lane];
    float2 je = sq[(size_t)(2 * BATCH + gw) * (EMBED / 2) + lane];
    float di = ue.x * ie.x + ue.y * ie.y;
    float dj = ue.x * je.x + ue.y * je.y;
    #pragma unroll
    for (int o = 16; o; o >>= 1) {
        di += __shfl_xor_sync(0xffffffffu, di, o);
        dj += __shfl_xor_sync(0xffffffffu, dj, o);
    }
    if (lane == 0) {
        out[gw]         = di * 0.0625f;   // (1/4)*(1/4)
        out[BATCH + gw] = dj * 0.0625f;
    }
}

extern "C" void kernel_launch(void* const* d_in, const int* in_sizes, int n_in,
                              void* d_out, int out_size) {
    const int*   user   = (const int*)d_in[0];
    const int*   item_i = (const int*)d_in[1];
    const int*   item_j = (const int*)d_in[2];
    const int*   esrc   = (const int*)d_in[5];
    const int*   edst   = (const int*)d_in[6];
    const float* evals  = (const float*)d_in[7];
    const float* eu     = (const float*)d_in[8];
    const float* ei     = (const float*)d_in[9];
    float* out = (float*)d_out;

    const int gb = (int)((N4 + 255) / 256);          // table-wide kernels
    const int hb = (HALF_E + 255) / 256;             // per-undirected-edge kernels
    const int wb = (NTOT * 32 + 255) / 256;          // warp-per-node gather
    const int qb = (NQ * 32 + 255) / 256;            // warp-per-query kernels

    k_init<<<gb, 256>>>(eu, ei, out);                        // 1
    k_regq<<<qb, 256>>>(user, item_i, item_j, eu, ei, out);  // 2

    // Build CSR fresh each launch.
    k_hist<<<hb, 256>>>(esrc, edst);                         // 3
    k_scan<<<SBLK, 256>>>();                                 // 4  (ncu capture slot)
    k_reorder<<<hb, 256>>>(esrc, edst, evals);               // 5

    // Layer 1: A16 -> B16 ; S_q += B16 at queried rows.
    k_gather<<<wb, 256>>>(0);                                // 6
    k_qacc<<<qb, 256>>>(user, item_i, item_j, 1);            // 7

    // Layer 2: B16 -> A16 ; S_q += A16 at queried rows.
    k_gather<<<wb, 256>>>(1);                                // 8
    k_qacc<<<qb, 256>>>(user, item_i, item_j, 0);            // 9

    // Layer 3 only at queried rows: S_q += gather(A16).
    k_qgather<<<qb, 256>>>(user, item_i, item_j);            // 10

    k_pred<<<(BATCH * 32) / 256, 256>>>(out);                // 11
}